// round 15
// baseline (speedup 1.0000x reference)
#include <cuda_runtime.h>
#include <cuda_bf16.h>

// x[16,64,256,256] f32, W[2,64], b[2]
//   e = exp(1x1conv(x) + b); s = e0+e1; out = e0 / boxsum3x3_replicate(s)
//
// Fully fused: one kernel, block = 16 full-width rows of one image.
//   Phase B: halo rows (2 x 256 px, clamped) -> s in smem, 2 px/thread via float2
//   Phase A: main 16 rows, 16 px/thread (4 float4 groups), __ldcs streaming;
//            e0 kept in registers, s -> smem
//   Phase C: 3x3 box from smem + divide, write out. No global scratch at all.
// R14 fix: s_sm must be 16B-aligned for float4 smem accesses (shared float
// arrays are only 4B-aligned by default -> "misaligned address" trap).

#define B 16
#define C 64
#define H 256
#define Wd 256
#define HW (H * Wd)            // 65536
#define TILE_ROWS 16
#define TILES_PER_IMG (H / TILE_ROWS)   // 16
#define NBLOCKS (B * TILES_PER_IMG)     // 256

__global__ __launch_bounds__(256) void fused_soft_det_kernel(
    const float* __restrict__ x,
    const float* __restrict__ Wc,
    const float* __restrict__ bias,
    float* __restrict__ out)
{
    __shared__ __align__(16) float ws[2 * C + 2];
    __shared__ __align__(16) float s_sm[TILE_ROWS + 2][Wd];   // 18 KB

    int tid = threadIdx.x;
    if (tid < 2 * C) ws[tid] = Wc[tid];
    if (tid < 2) ws[2 * C + tid] = bias[tid];
    __syncthreads();

    int bidx = blockIdx.x >> 4;          // image 0..15
    int tile = blockIdx.x & 15;          // tile within image
    int tile_start = tile * TILE_ROWS;

    float b0 = ws[2 * C], b1 = ws[2 * C + 1];

    // ---------- Phase B: halo rows (clamped at image edges) ----------
    {
        int hsel = tid >> 7;                         // 0 = top halo, 1 = bottom halo
        int hcol = (tid & 127) * 2;                  // pixel column (pairs)
        int hrow_top = tile_start - 1 < 0 ? 0 : tile_start - 1;
        int hrow_bot = tile_start + TILE_ROWS > H - 1 ? H - 1 : tile_start + TILE_ROWS;
        int hrow = hsel == 0 ? hrow_top : hrow_bot;

        const float2* x2 = reinterpret_cast<const float2*>(x);
        size_t hbase = (size_t)bidx * C * (HW / 2)
                     + (size_t)hrow * (Wd / 2) + (hcol >> 1);

        float h0x = 0.f, h0y = 0.f, h1x = 0.f, h1y = 0.f;
#pragma unroll 8
        for (int c = 0; c < C; c++) {
            float2 v = x2[hbase + (size_t)c * (HW / 2)];
            float w0 = ws[c], w1 = ws[C + c];
            h0x = fmaf(v.x, w0, h0x);
            h0y = fmaf(v.y, w0, h0y);
            h1x = fmaf(v.x, w1, h1x);
            h1y = fmaf(v.y, w1, h1y);
        }
        int srow = hsel == 0 ? 0 : TILE_ROWS + 1;
        s_sm[srow][hcol]     = __expf(h0x + b0) + __expf(h1x + b1);
        s_sm[srow][hcol + 1] = __expf(h0y + b0) + __expf(h1y + b1);
    }

    // ---------- Phase A: main tile contraction, e0 in regs, s -> smem ----------
    int trow = tid >> 6;                 // 0..3
    int cg = tid & 63;                   // float4 column group 0..63

    const float4* x4 = reinterpret_cast<const float4*>(x);
    size_t mbase = (size_t)bidx * C * (HW / 4)
                 + (size_t)(tile_start + trow) * (Wd / 4) + cg;

    float4 a0[4], a1[4];
#pragma unroll
    for (int k = 0; k < 4; k++) {
        a0[k] = make_float4(0.f, 0.f, 0.f, 0.f);
        a1[k] = make_float4(0.f, 0.f, 0.f, 0.f);
    }

#pragma unroll 4
    for (int c = 0; c < C; c++) {
        const float4* xc = x4 + mbase + (size_t)c * (HW / 4);
        float4 v[4];
#pragma unroll
        for (int k = 0; k < 4; k++)
            v[k] = __ldcs(xc + k * 4 * (Wd / 4));    // k advances 4 rows
        float w0 = ws[c];
        float w1 = ws[C + c];
#pragma unroll
        for (int k = 0; k < 4; k++) {
            a0[k].x = fmaf(v[k].x, w0, a0[k].x);
            a0[k].y = fmaf(v[k].y, w0, a0[k].y);
            a0[k].z = fmaf(v[k].z, w0, a0[k].z);
            a0[k].w = fmaf(v[k].w, w0, a0[k].w);
            a1[k].x = fmaf(v[k].x, w1, a1[k].x);
            a1[k].y = fmaf(v[k].y, w1, a1[k].y);
            a1[k].z = fmaf(v[k].z, w1, a1[k].z);
            a1[k].w = fmaf(v[k].w, w1, a1[k].w);
        }
    }

    float4 e0[4];
#pragma unroll
    for (int k = 0; k < 4; k++) {
        e0[k].x = __expf(a0[k].x + b0);
        e0[k].y = __expf(a0[k].y + b0);
        e0[k].z = __expf(a0[k].z + b0);
        e0[k].w = __expf(a0[k].w + b0);
        float4 s;
        s.x = e0[k].x + __expf(a1[k].x + b1);
        s.y = e0[k].y + __expf(a1[k].y + b1);
        s.z = e0[k].z + __expf(a1[k].z + b1);
        s.w = e0[k].w + __expf(a1[k].w + b1);
        int r = k * 4 + trow;                        // tile row 0..15
        *reinterpret_cast<float4*>(&s_sm[r + 1][cg * 4]) = s;
    }

    __syncthreads();

    // ---------- Phase C: 3x3 box from smem + divide ----------
    int w = cg * 4;
#pragma unroll
    for (int k = 0; k < 4; k++) {
        int r = k * 4 + trow;                        // smem rows r..r+2
        float4 acc = make_float4(0.f, 0.f, 0.f, 0.f);
#pragma unroll
        for (int dr = 0; dr < 3; dr++) {
            const float* row = s_sm[r + dr];
            float4 v = *reinterpret_cast<const float4*>(row + w);
            float l  = (w == 0)      ? v.x : row[w - 1];
            float rr = (w + 4 == Wd) ? v.w : row[w + 4];
            acc.x += l   + v.x + v.y;
            acc.y += v.x + v.y + v.z;
            acc.z += v.y + v.z + v.w;
            acc.w += v.z + v.w + rr;
        }
        float4 o;
        o.x = e0[k].x / acc.x;
        o.y = e0[k].y / acc.y;
        o.z = e0[k].z / acc.z;
        o.w = e0[k].w / acc.w;
        reinterpret_cast<float4*>(out)[(size_t)bidx * (HW / 4)
                                       + (size_t)(tile_start + r) * (Wd / 4) + cg] = o;
    }
}

extern "C" void kernel_launch(void* const* d_in, const int* in_sizes, int n_in,
                              void* d_out, int out_size)
{
    const float* x  = (const float*)d_in[0];
    const float* Wc = (const float*)d_in[1];
    const float* bs = (const float*)d_in[2];
    float* out = (float*)d_out;

    fused_soft_det_kernel<<<NBLOCKS, 256>>>(x, Wc, bs, out);
}

// round 16
// speedup vs baseline: 1.0793x; 1.0793x over previous
#include <cuda_runtime.h>
#include <cuda_bf16.h>

// x[16,64,256,256] f32, W[2,64], b[2]
//   e = exp(1x1conv(x) + b); s = e0+e1; out = e0 / boxsum3x3_replicate(s)
//
// Persistent single kernel with software grid barrier:
//   Phase 1: channel contraction, 16 contiguous px/thread (measured-best K1
//            shape), __ldcs x reads; s -> global scratch (4 MB, L2-resident);
//            e0 stays in REGISTERS (no round-trip).
//   Barrier: generation-counter grid barrier (all 256 CTAs co-resident via
//            __launch_bounds__(256,2): 2/SM * 148 = 296 >= 256).
//   Phase 2: 3x3 replicate box from L2-hot s + divide by reg-resident e0.

#define B 16
#define C 64
#define H 256
#define Wd 256
#define HW (H * Wd)          // 65536
#define NPIX (B * HW)        // 1048576
#define NP16 (NPIX / 16)     // 65536
#define NBLOCKS (NP16 / 256) // 256

__device__ float g_s[NPIX];
__device__ unsigned int g_bar;   // zero-initialized; monotonic across launches

__global__ __launch_bounds__(256, 2) void soft_det_persistent(
    const float* __restrict__ x,
    const float* __restrict__ Wc,
    const float* __restrict__ bias,
    float* __restrict__ out)
{
    __shared__ float ws[2 * C + 2];
    int tid = threadIdx.x;
    if (tid < 2 * C) ws[tid] = Wc[tid];
    if (tid < 2) ws[2 * C + tid] = bias[tid];
    __syncthreads();

    int p16 = blockIdx.x * 256 + tid;         // 16-pixel group index
    int bidx = p16 >> 12;                     // image index
    int g = (p16 & 4095) * 4;                 // first float4 group in image
                                              // (16 contiguous px in one row)
    const float4* xb = reinterpret_cast<const float4*>(x)
                     + (size_t)bidx * C * (HW / 4) + g;

    // ---------------- Phase 1: contraction + exp ----------------
    float4 a0[4], a1[4];
#pragma unroll
    for (int k = 0; k < 4; k++) {
        a0[k] = make_float4(0.f, 0.f, 0.f, 0.f);
        a1[k] = make_float4(0.f, 0.f, 0.f, 0.f);
    }

#pragma unroll 4
    for (int c = 0; c < C; c++) {
        const float4* xc = xb + (size_t)c * (HW / 4);
        float4 v[4];
#pragma unroll
        for (int k = 0; k < 4; k++)
            v[k] = __ldcs(xc + k);
        float w0 = ws[c];
        float w1 = ws[C + c];
#pragma unroll
        for (int k = 0; k < 4; k++) {
            a0[k].x = fmaf(v[k].x, w0, a0[k].x);
            a0[k].y = fmaf(v[k].y, w0, a0[k].y);
            a0[k].z = fmaf(v[k].z, w0, a0[k].z);
            a0[k].w = fmaf(v[k].w, w0, a0[k].w);
            a1[k].x = fmaf(v[k].x, w1, a1[k].x);
            a1[k].y = fmaf(v[k].y, w1, a1[k].y);
            a1[k].z = fmaf(v[k].z, w1, a1[k].z);
            a1[k].w = fmaf(v[k].w, w1, a1[k].w);
        }
    }

    float b0 = ws[2 * C], b1 = ws[2 * C + 1];

    float4 e0[4];
    float4* sp = reinterpret_cast<float4*>(g_s) + p16 * 4;
#pragma unroll
    for (int k = 0; k < 4; k++) {
        e0[k].x = __expf(a0[k].x + b0);
        e0[k].y = __expf(a0[k].y + b0);
        e0[k].z = __expf(a0[k].z + b0);
        e0[k].w = __expf(a0[k].w + b0);
        float4 s;
        s.x = e0[k].x + __expf(a1[k].x + b1);
        s.y = e0[k].y + __expf(a1[k].y + b1);
        s.z = e0[k].z + __expf(a1[k].z + b1);
        s.w = e0[k].w + __expf(a1[k].w + b1);
        sp[k] = s;                            // default policy -> L2 resident
    }

    // ---------------- Grid barrier (generation counter) ----------------
    __syncthreads();                          // all block stores issued
    if (tid == 0) {
        __threadfence();                      // make s visible gpu-wide
        unsigned int old = atomicAdd(&g_bar, 1u);
        unsigned int target = (old / NBLOCKS + 1u) * NBLOCKS;
        for (;;) {
            unsigned int cur;
            asm volatile("ld.acquire.gpu.global.u32 %0, [%1];"
                         : "=r"(cur) : "l"(&g_bar));
            if (cur >= target) break;
            __nanosleep(64);
        }
    }
    __syncthreads();                          // publish to whole block

    // ---------------- Phase 2: 3x3 box + divide ----------------
    {
        int row = g >> 6;                     // 64 float4 groups per row
        int w = (g & 63) * 4;                 // first pixel column (0..240)
        const float* sb = g_s + bidx * HW;

        float acc[16];
#pragma unroll
        for (int i = 0; i < 16; i++) acc[i] = 0.f;

#pragma unroll
        for (int dh = -1; dh <= 1; dh++) {
            int hh = row + dh;
            hh = hh < 0 ? 0 : (hh > H - 1 ? H - 1 : hh);
            const float* r = sb + hh * Wd;

            float sarr[18];
            float4 v0 = *reinterpret_cast<const float4*>(r + w);
            float4 v1 = *reinterpret_cast<const float4*>(r + w + 4);
            float4 v2 = *reinterpret_cast<const float4*>(r + w + 8);
            float4 v3 = *reinterpret_cast<const float4*>(r + w + 12);
            sarr[0]  = (w == 0) ? v0.x : r[w - 1];
            sarr[1]  = v0.x; sarr[2]  = v0.y; sarr[3]  = v0.z; sarr[4]  = v0.w;
            sarr[5]  = v1.x; sarr[6]  = v1.y; sarr[7]  = v1.z; sarr[8]  = v1.w;
            sarr[9]  = v2.x; sarr[10] = v2.y; sarr[11] = v2.z; sarr[12] = v2.w;
            sarr[13] = v3.x; sarr[14] = v3.y; sarr[15] = v3.z; sarr[16] = v3.w;
            sarr[17] = (w + 16 == Wd) ? v3.w : r[w + 16];

#pragma unroll
            for (int i = 0; i < 16; i++)
                acc[i] += sarr[i] + sarr[i + 1] + sarr[i + 2];
        }

        float4* op = reinterpret_cast<float4*>(out) + p16 * 4;
#pragma unroll
        for (int k = 0; k < 4; k++) {
            float4 o;
            o.x = e0[k].x / acc[k * 4 + 0];
            o.y = e0[k].y / acc[k * 4 + 1];
            o.z = e0[k].z / acc[k * 4 + 2];
            o.w = e0[k].w / acc[k * 4 + 3];
            op[k] = o;
        }
    }
}

extern "C" void kernel_launch(void* const* d_in, const int* in_sizes, int n_in,
                              void* d_out, int out_size)
{
    const float* x  = (const float*)d_in[0];
    const float* Wc = (const float*)d_in[1];
    const float* bs = (const float*)d_in[2];
    float* out = (float*)d_out;

    soft_det_persistent<<<NBLOCKS, 256>>>(x, Wc, bs, out);
}